// round 15
// baseline (speedup 1.0000x reference)
#include <cuda_runtime.h>
#include <cstdint>

#define N_ENTITIES 100000
#define N_USERS    50000
#define N_FACTORS  4
#define N_RELATIONS 32
#define N_REL_USED 31
#define N_META     8
#define CHANNEL    64
#define N_EDGES    1600000
#define NNZ_CNT    1000000

#define HW_PER_BLOCK 16                     // 256 threads / 16 lanes
#define SLOT 96                             // slots per head (deg~Poisson(16))

// ---- K1 split ----
#define ZERO_B   64                         // zero out_user
#define BIN_B    280                        // bin edges by head
#define ATT_B    888                        // attention table (latency-bound)
#define K1_BLOCKS (ZERO_B + BIN_B + ATT_B + 1)   // +1 disen

#define TILE_E 64
#define ATT_TILES ((N_ENTITIES + TILE_E - 1) / TILE_E)

// ---- K2 split ----
#define GATH_B 740                          // edge gather (L2-read bound)
#define SPMM_B 444                          // spmm scatter (atomic bound)
#define K2_BLOCKS (GATH_B + SPMM_B)

// ---- K3 split ----
#define CNTZ_B  391                         // reset g_ecnt for next call
#define USERF_B 6250
#define K3_BLOCKS (CNTZ_B + USERF_B)

// ------------------------- device-global scratch ---------------------------
// g_ecnt contract: zero at kernel_launch entry (zero-init at module load;
// reset by K3 each call) -> deterministic on every call.
__device__ int   g_ecnt[N_ENTITIES];                 // per-head cursor == degree
__device__ int2  g_slot[(size_t)N_ENTITIES * SLOT];  // {tail, rel} bins
__device__ float g_disen[N_FACTORS * CHANNEL];
__device__ float g_att[N_ENTITIES * N_REL_USED];     // sigmoid(ent[h].rel[r])

__device__ __forceinline__ void red_add_v4(float* p, float x, float y, float z, float w) {
    asm volatile("red.global.add.v4.f32 [%0], {%1,%2,%3,%4};"
                 :: "l"(p), "f"(x), "f"(y), "f"(z), "f"(w) : "memory");
}

// ---------------------------------------------------------------------------
// K1: zero out_user | bin edges by head | att table | disen
//     att: 4 channel-passes with rrel[4] -> <=64 regs -> 4 blocks/SM
// ---------------------------------------------------------------------------
__global__ void __launch_bounds__(256, 4)
k1_kernel(const float* __restrict__ ent,
          const int*   __restrict__ head,
          const int*   __restrict__ tail,
          const int*   __restrict__ etype,
          const float* __restrict__ relw,
          const float* __restrict__ datt,
          const float* __restrict__ weight,
          float4* __restrict__ out_user4) {
    int b = blockIdx.x;

    if (b < ZERO_B) {
        // ---- zero user output (entity output plain-stored by gather) ----
        const int total4 = N_USERS * CHANNEL / 4;
        int i0     = b * 256 + threadIdx.x;
        int stride = ZERO_B * 256;
        for (int i = i0; i < total4; i += stride)
            out_user4[i] = make_float4(0.f, 0.f, 0.f, 0.f);

    } else if (b < ZERO_B + BIN_B) {
        // ---- bin edges: thread per edge, fixed-slot cursor ----
        int t0      = (b - ZERO_B) * 256 + threadIdx.x;
        int tstride = BIN_B * 256;
        for (int e = t0; e < N_EDGES; e += tstride) {
            int h = __ldg(&head[e]);
            int pos = atomicAdd(&g_ecnt[h], 1);
            g_slot[(size_t)h * SLOT + pos] =
                make_int2(__ldg(&tail[e]), __ldg(&etype[e]) - 1);
        }

    } else if (b < ZERO_B + BIN_B + ATT_B) {
        // ---- attention table: tile staging, 4-pass channel split ----
        __shared__ float s_ent[TILE_E * CHANNEL];     // 16 KB tile
        int lane = threadIdx.x & 31;
        int wid  = threadIdx.x >> 5;
        bool has_rel = (lane < N_REL_USED);
        const float4* rw = (const float4*)&relw[(has_rel ? lane : 0) * CHANNEL];

        int tile0 = b - (ZERO_B + BIN_B);
        for (int tile = tile0; tile < ATT_TILES; tile += ATT_B) {
            int base = tile * TILE_E;
            int cnt  = min(TILE_E, N_ENTITIES - base);

            __syncthreads();
            const float4* src = (const float4*)&ent[(size_t)base * CHANNEL];
            for (int i = threadIdx.x; i < cnt * (CHANNEL / 4); i += 256)
                ((float4*)s_ent)[i] = __ldg(&src[i]);
            __syncthreads();

            float part[8];
            #pragma unroll
            for (int i = 0; i < 8; i++) part[i] = 0.0f;

            #pragma unroll
            for (int pass = 0; pass < 4; pass++) {
                float4 rrel[4];
                #pragma unroll
                for (int i = 0; i < 4; i++)
                    rrel[i] = has_rel ? __ldg(&rw[pass * 4 + i])
                                      : make_float4(0.f, 0.f, 0.f, 0.f);
                #pragma unroll
                for (int k8 = 0; k8 < 8; k8++) {
                    int k = wid + k8 * 8;
                    const float4* row =
                        (const float4*)&s_ent[k * CHANNEL + pass * 16];
                    float d0 = 0.f, d1 = 0.f;
                    #pragma unroll
                    for (int i = 0; i < 4; i++) {
                        float4 a = row[i];                // broadcast LDS.128
                        d0 += a.x * rrel[i].x + a.z * rrel[i].z;
                        d1 += a.y * rrel[i].y + a.w * rrel[i].w;
                    }
                    part[k8] += d0 + d1;
                }
            }

            #pragma unroll
            for (int k8 = 0; k8 < 8; k8++) {
                int k = wid + k8 * 8;
                if (has_rel && k < cnt)
                    g_att[(size_t)(base + k) * N_REL_USED + lane] =
                        1.0f / (1.0f + __expf(-part[k8]));
            }
        }

    } else {
        // ---- disen_weight = softmax(disen_weight_att, -1) @ weight ----
        int c = threadIdx.x;
        if (c >= CHANNEL) return;
        #pragma unroll
        for (int f = 0; f < N_FACTORS; f++) {
            float a[N_META];
            float m = -1e30f;
            #pragma unroll
            for (int j = 0; j < N_META; j++) { a[j] = datt[f * N_META + j]; m = fmaxf(m, a[j]); }
            float s = 0.0f;
            #pragma unroll
            for (int j = 0; j < N_META; j++) { a[j] = __expf(a[j] - m); s += a[j]; }
            float inv = 1.0f / s;
            float acc = 0.0f;
            #pragma unroll
            for (int j = 0; j < N_META; j++) acc += a[j] * inv * weight[j * CHANNEL + c];
            g_disen[f * CHANNEL + c] = acc;
        }
    }
}

// ---------------------------------------------------------------------------
// K2: edge GATHER (full warp per head, two halves on even/odd slots, shfl
//     merge, fused mean, plain store) | spmm scatter (atomic pipe)
// ---------------------------------------------------------------------------
__global__ void __launch_bounds__(256)
k2_kernel(const float* __restrict__ ent,
          const int*   __restrict__ mrow,
          const int*   __restrict__ mcol,
          const float* __restrict__ mval,
          const float* __restrict__ relw,
          float* __restrict__ out_ent,
          float* __restrict__ out_user) {

    if (blockIdx.x < GATH_B) {
        // ---------------- edge gather ----------------
        __shared__ float s_rel[N_REL_USED * CHANNEL];
        for (int i = threadIdx.x; i < N_REL_USED * CHANNEL; i += blockDim.x)
            s_rel[i] = relw[i];
        __syncthreads();

        int lane = threadIdx.x & 31;
        int li   = lane & 15;
        int half = lane >> 4;

        int w      = blockIdx.x * 8 + (threadIdx.x >> 5);
        int stride = GATH_B * 8;

        for (int h = w; h < N_ENTITIES; h += stride) {
            int deg = __ldg(&g_ecnt[h]);
            const int2*  slot = &g_slot[(size_t)h * SLOT];
            const float* arow = &g_att[(size_t)h * N_REL_USED];

            float4 acc = make_float4(0.f, 0.f, 0.f, 0.f);
            #pragma unroll 2
            for (int j = half; j < deg; j += 2) {
                int2  p   = __ldg(&slot[j]);                  // uniform per half
                float att = __ldg(&arow[p.y]);
                float4 et = __ldg((const float4*)&ent[(size_t)p.x * CHANNEL + li * 4]);
                float4 rl = *(const float4*)&s_rel[p.y * CHANNEL + li * 4];
                acc.x += att * et.x * rl.x;
                acc.y += att * et.y * rl.y;
                acc.z += att * et.z * rl.z;
                acc.w += att * et.w * rl.w;
            }
            acc.x += __shfl_xor_sync(0xFFFFFFFFu, acc.x, 16);
            acc.y += __shfl_xor_sync(0xFFFFFFFFu, acc.y, 16);
            acc.z += __shfl_xor_sync(0xFFFFFFFFu, acc.z, 16);
            acc.w += __shfl_xor_sync(0xFFFFFFFFu, acc.w, 16);

            if (half == 0) {
                float inv = 1.0f / fmaxf((float)deg, 1.0f);
                float4* o = (float4*)&out_ent[(size_t)h * CHANNEL + li * 4];
                *o = make_float4(acc.x * inv, acc.y * inv, acc.z * inv, acc.w * inv);
            }
        }
    } else {
        // ---------------- spmm scatter ----------------
        int li     = threadIdx.x & 15;
        int hw     = (blockIdx.x - GATH_B) * HW_PER_BLOCK + (threadIdx.x >> 4);
        int stride = SPMM_B * HW_PER_BLOCK;

        for (int i = hw; i < NNZ_CNT; i += stride) {
            int   r = __ldg(&mrow[i]);
            int   c = __ldg(&mcol[i]);
            float v = __ldg(&mval[i]);
            float4 e4 = __ldg((const float4*)&ent[(size_t)c * CHANNEL + li * 4]);
            red_add_v4(&out_user[(size_t)r * CHANNEL + li * 4],
                       v * e4.x, v * e4.y, v * e4.z, v * e4.w);
        }
    }
}

// ---------------------------------------------------------------------------
// K3: reset g_ecnt (lifecycle) | user softmax-blend
// ---------------------------------------------------------------------------
__global__ void __launch_bounds__(256)
k3_kernel(const float* __restrict__ user_emb,
          const float* __restrict__ latent,
          float* __restrict__ out_user) {
    int b = blockIdx.x;

    if (b < CNTZ_B) {
        int i = b * 256 + threadIdx.x;
        if (i < N_ENTITIES) g_ecnt[i] = 0;

    } else {
        __shared__ float s_lat[N_FACTORS * CHANNEL];
        __shared__ float s_dis[N_FACTORS * CHANNEL];
        for (int i = threadIdx.x; i < N_FACTORS * CHANNEL; i += blockDim.x) {
            s_lat[i] = latent[i];
            s_dis[i] = g_disen[i];
        }
        __syncthreads();

        int u    = (b - CNTZ_B) * 8 + (threadIdx.x >> 5);
        int lane = threadIdx.x & 31;
        if (u >= N_USERS) return;

        float2 ue = *(const float2*)&user_emb[(size_t)u * CHANNEL + lane * 2];

        float s[N_FACTORS];
        #pragma unroll
        for (int f = 0; f < N_FACTORS; f++) {
            float p = ue.x * s_lat[f * CHANNEL + lane * 2]
                    + ue.y * s_lat[f * CHANNEL + lane * 2 + 1];
            #pragma unroll
            for (int o = 16; o > 0; o >>= 1) p += __shfl_xor_sync(0xFFFFFFFFu, p, o);
            s[f] = p;
        }
        float m = fmaxf(fmaxf(s[0], s[1]), fmaxf(s[2], s[3]));
        float sum = 0.0f;
        #pragma unroll
        for (int f = 0; f < N_FACTORS; f++) { s[f] = __expf(s[f] - m); sum += s[f]; }
        float inv = 1.0f / sum;

        float cx = 0.0f, cy = 0.0f;
        #pragma unroll
        for (int f = 0; f < N_FACTORS; f++) {
            float sc = s[f] * inv;
            cx += sc * s_dis[f * CHANNEL + lane * 2];
            cy += sc * s_dis[f * CHANNEL + lane * 2 + 1];
        }

        float2* p = (float2*)&out_user[(size_t)u * CHANNEL + lane * 2];
        float2 a = *p;
        a.x = a.x * (1.0f + cx);
        a.y = a.y * (1.0f + cy);
        *p = a;
    }
}

// ---------------------------------------------------------------------------
extern "C" void kernel_launch(void* const* d_in, const int* in_sizes, int n_in,
                              void* d_out, int out_size)
{
    const float* entity_emb = (const float*)d_in[0];
    const float* user_emb   = (const float*)d_in[1];
    const float* latent_emb = (const float*)d_in[2];
    const int*   head       = (const int*)d_in[3];
    const int*   tail       = (const int*)d_in[4];
    const int*   edge_type  = (const int*)d_in[5];
    const int*   mat_row    = (const int*)d_in[6];
    const int*   mat_col    = (const int*)d_in[7];
    const float* mat_val    = (const float*)d_in[8];
    const float* rel_w      = (const float*)d_in[9];
    const float* weight     = (const float*)d_in[10];
    const float* disen_att  = (const float*)d_in[11];

    float* out      = (float*)d_out;
    float* out_ent  = out;                                 // (N_ENTITIES, 64)
    float* out_user = out + (size_t)N_ENTITIES * CHANNEL;  // (N_USERS, 64)

    k1_kernel<<<K1_BLOCKS, 256>>>(entity_emb, head, tail, edge_type,
                                  rel_w, disen_att, weight,
                                  (float4*)out_user);

    k2_kernel<<<K2_BLOCKS, 256>>>(entity_emb, mat_row, mat_col, mat_val,
                                  rel_w, out_ent, out_user);

    k3_kernel<<<K3_BLOCKS, 256>>>(user_emb, latent_emb, out_user);
}

// round 16
// speedup vs baseline: 1.1208x; 1.1208x over previous
#include <cuda_runtime.h>
#include <cstdint>

#define N_ENTITIES 100000
#define N_USERS    50000
#define N_FACTORS  4
#define N_RELATIONS 32
#define N_REL_USED 31
#define N_META     8
#define CHANNEL    64
#define N_EDGES    1600000
#define NNZ_CNT    1000000

#define SLOT   96                           // edge slots per head (Poisson 16)
#define SLOT_U 64                           // nnz slots per user (Poisson 20)

// ---- K1 split ----
#define BINE_B  280                         // bin edges by head
#define BINU_B  140                         // bin nnz by user
#define ATT_B   888                         // attention table (latency-bound)
#define K1_BLOCKS (BINE_B + BINU_B + ATT_B + 1)   // +1 disen

#define TILE_E 64
#define ATT_TILES ((N_ENTITIES + TILE_E - 1) / TILE_E)

// ---- K2 split ----
#define GATHE_B 740                         // edge gather
#define GATHU_B 444                         // user gather + blend
#define K2_BLOCKS (GATHE_B + GATHU_B)

// ------------------------- device-global scratch ---------------------------
// cursor contract: zero at kernel_launch entry (zero-init at module load;
// reset by K2 after consumption) -> deterministic on every call.
__device__ int   g_ecnt[N_ENTITIES];                   // per-head cursor/degree
__device__ int   g_ucnt[N_USERS];                      // per-user cursor/degree
__device__ int2  g_slot [(size_t)N_ENTITIES * SLOT];   // {tail, rel}
__device__ int2  g_uslot[(size_t)N_USERS * SLOT_U];    // {col, bits(val)}
__device__ float g_disen[N_FACTORS * CHANNEL];
__device__ float g_att[N_ENTITIES * N_REL_USED];       // sigmoid(ent[h].rel[r])

// ---------------------------------------------------------------------------
// K1: bin edges | bin nnz | att table | disen
// ---------------------------------------------------------------------------
__global__ void __launch_bounds__(256)
k1_kernel(const float* __restrict__ ent,
          const int*   __restrict__ head,
          const int*   __restrict__ tail,
          const int*   __restrict__ etype,
          const int*   __restrict__ mrow,
          const int*   __restrict__ mcol,
          const float* __restrict__ mval,
          const float* __restrict__ relw,
          const float* __restrict__ datt,
          const float* __restrict__ weight) {
    int b = blockIdx.x;

    if (b < BINE_B) {
        // ---- bin edges: thread per edge, fixed-slot cursor ----
        int t0      = b * 256 + threadIdx.x;
        int tstride = BINE_B * 256;
        for (int e = t0; e < N_EDGES; e += tstride) {
            int h = __ldg(&head[e]);
            int pos = atomicAdd(&g_ecnt[h], 1);
            g_slot[(size_t)h * SLOT + pos] =
                make_int2(__ldg(&tail[e]), __ldg(&etype[e]) - 1);
        }

    } else if (b < BINE_B + BINU_B) {
        // ---- bin nnz by user ----
        int t0      = (b - BINE_B) * 256 + threadIdx.x;
        int tstride = BINU_B * 256;
        for (int i = t0; i < NNZ_CNT; i += tstride) {
            int r = __ldg(&mrow[i]);
            int pos = atomicAdd(&g_ucnt[r], 1);
            g_uslot[(size_t)r * SLOT_U + pos] =
                make_int2(__ldg(&mcol[i]), __float_as_int(__ldg(&mval[i])));
        }

    } else if (b < BINE_B + BINU_B + ATT_B) {
        // ---- attention table: tile staging, 2-pass channel split (R14) ----
        __shared__ float s_ent[TILE_E * CHANNEL];     // 16 KB tile
        int lane = threadIdx.x & 31;
        int wid  = threadIdx.x >> 5;
        bool has_rel = (lane < N_REL_USED);
        const float4* rw = (const float4*)&relw[(has_rel ? lane : 0) * CHANNEL];

        int tile0 = b - (BINE_B + BINU_B);
        for (int tile = tile0; tile < ATT_TILES; tile += ATT_B) {
            int base = tile * TILE_E;
            int cnt  = min(TILE_E, N_ENTITIES - base);

            __syncthreads();
            const float4* src = (const float4*)&ent[(size_t)base * CHANNEL];
            for (int i = threadIdx.x; i < cnt * (CHANNEL / 4); i += 256)
                ((float4*)s_ent)[i] = __ldg(&src[i]);
            __syncthreads();

            float part[8];
            float4 rrel[8];

            #pragma unroll
            for (int i = 0; i < 8; i++)
                rrel[i] = has_rel ? __ldg(&rw[i]) : make_float4(0.f, 0.f, 0.f, 0.f);
            #pragma unroll
            for (int k8 = 0; k8 < 8; k8++) {
                int k = wid + k8 * 8;
                const float4* row = (const float4*)&s_ent[k * CHANNEL];
                float d0 = 0.f, d1 = 0.f;
                #pragma unroll
                for (int i = 0; i < 8; i++) {
                    float4 a = row[i];
                    d0 += a.x * rrel[i].x + a.z * rrel[i].z;
                    d1 += a.y * rrel[i].y + a.w * rrel[i].w;
                }
                part[k8] = d0 + d1;
            }

            #pragma unroll
            for (int i = 0; i < 8; i++)
                rrel[i] = has_rel ? __ldg(&rw[8 + i]) : make_float4(0.f, 0.f, 0.f, 0.f);
            #pragma unroll
            for (int k8 = 0; k8 < 8; k8++) {
                int k = wid + k8 * 8;
                const float4* row = (const float4*)&s_ent[k * CHANNEL + 32];
                float d0 = 0.f, d1 = 0.f;
                #pragma unroll
                for (int i = 0; i < 8; i++) {
                    float4 a = row[i];
                    d0 += a.x * rrel[i].x + a.z * rrel[i].z;
                    d1 += a.y * rrel[i].y + a.w * rrel[i].w;
                }
                float d = part[k8] + d0 + d1;
                if (has_rel && k < cnt)
                    g_att[(size_t)(base + k) * N_REL_USED + lane] =
                        1.0f / (1.0f + __expf(-d));
            }
        }

    } else {
        // ---- disen_weight = softmax(disen_weight_att, -1) @ weight ----
        int c = threadIdx.x;
        if (c >= CHANNEL) return;
        #pragma unroll
        for (int f = 0; f < N_FACTORS; f++) {
            float a[N_META];
            float m = -1e30f;
            #pragma unroll
            for (int j = 0; j < N_META; j++) { a[j] = datt[f * N_META + j]; m = fmaxf(m, a[j]); }
            float s = 0.0f;
            #pragma unroll
            for (int j = 0; j < N_META; j++) { a[j] = __expf(a[j] - m); s += a[j]; }
            float inv = 1.0f / s;
            float acc = 0.0f;
            #pragma unroll
            for (int j = 0; j < N_META; j++) acc += a[j] * inv * weight[j * CHANNEL + c];
            g_disen[f * CHANNEL + c] = acc;
        }
    }
}

// ---------------------------------------------------------------------------
// K2: edge gather (warp/head, 2-half MLP, fused mean, plain store)
//   | user gather (warp/user, 2-half MLP, fused softmax-blend, plain store)
//   Both reset their cursors after consumption (lifecycle).
// ---------------------------------------------------------------------------
__global__ void __launch_bounds__(256)
k2_kernel(const float* __restrict__ ent,
          const float* __restrict__ user_emb,
          const float* __restrict__ latent,
          const float* __restrict__ relw,
          float* __restrict__ out_ent,
          float* __restrict__ out_user) {
    int lane = threadIdx.x & 31;
    int li   = lane & 15;
    int half = lane >> 4;

    if (blockIdx.x < GATHE_B) {
        // ---------------- edge gather ----------------
        __shared__ float s_rel[N_REL_USED * CHANNEL];
        for (int i = threadIdx.x; i < N_REL_USED * CHANNEL; i += blockDim.x)
            s_rel[i] = relw[i];
        __syncthreads();

        int w      = blockIdx.x * 8 + (threadIdx.x >> 5);
        int stride = GATHE_B * 8;

        for (int h = w; h < N_ENTITIES; h += stride) {
            int deg = __ldg(&g_ecnt[h]);
            const int2*  slot = &g_slot[(size_t)h * SLOT];
            const float* arow = &g_att[(size_t)h * N_REL_USED];

            float4 acc = make_float4(0.f, 0.f, 0.f, 0.f);
            #pragma unroll 2
            for (int j = half; j < deg; j += 2) {
                int2  p   = __ldg(&slot[j]);
                float att = __ldg(&arow[p.y]);
                float4 et = __ldg((const float4*)&ent[(size_t)p.x * CHANNEL + li * 4]);
                float4 rl = *(const float4*)&s_rel[p.y * CHANNEL + li * 4];
                acc.x += att * et.x * rl.x;
                acc.y += att * et.y * rl.y;
                acc.z += att * et.z * rl.z;
                acc.w += att * et.w * rl.w;
            }
            acc.x += __shfl_xor_sync(0xFFFFFFFFu, acc.x, 16);
            acc.y += __shfl_xor_sync(0xFFFFFFFFu, acc.y, 16);
            acc.z += __shfl_xor_sync(0xFFFFFFFFu, acc.z, 16);
            acc.w += __shfl_xor_sync(0xFFFFFFFFu, acc.w, 16);

            if (half == 0) {
                float inv = 1.0f / fmaxf((float)deg, 1.0f);
                float4* o = (float4*)&out_ent[(size_t)h * CHANNEL + li * 4];
                *o = make_float4(acc.x * inv, acc.y * inv, acc.z * inv, acc.w * inv);
            }
            if (lane == 0) g_ecnt[h] = 0;      // reset after consumption
        }
    } else {
        // ---------------- user gather + softmax blend ----------------
        __shared__ float s_lat[N_FACTORS * CHANNEL];
        __shared__ float s_dis[N_FACTORS * CHANNEL];
        for (int i = threadIdx.x; i < N_FACTORS * CHANNEL; i += blockDim.x) {
            s_lat[i] = latent[i];
            s_dis[i] = g_disen[i];
        }
        __syncthreads();

        int w      = (blockIdx.x - GATHE_B) * 8 + (threadIdx.x >> 5);
        int stride = GATHU_B * 8;

        for (int u = w; u < N_USERS; u += stride) {
            int deg = __ldg(&g_ucnt[u]);
            const int2* slot = &g_uslot[(size_t)u * SLOT_U];

            float4 acc = make_float4(0.f, 0.f, 0.f, 0.f);
            #pragma unroll 2
            for (int j = half; j < deg; j += 2) {
                int2  p = __ldg(&slot[j]);
                float v = __int_as_float(p.y);
                float4 e = __ldg((const float4*)&ent[(size_t)p.x * CHANNEL + li * 4]);
                acc.x += v * e.x;
                acc.y += v * e.y;
                acc.z += v * e.z;
                acc.w += v * e.w;
            }
            acc.x += __shfl_xor_sync(0xFFFFFFFFu, acc.x, 16);
            acc.y += __shfl_xor_sync(0xFFFFFFFFu, acc.y, 16);
            acc.z += __shfl_xor_sync(0xFFFFFFFFu, acc.z, 16);
            acc.w += __shfl_xor_sync(0xFFFFFFFFu, acc.w, 16);

            // score softmax: each 16-lane half holds the full row (li*4)
            float4 ue = __ldg((const float4*)&user_emb[(size_t)u * CHANNEL + li * 4]);
            float s[N_FACTORS];
            #pragma unroll
            for (int f = 0; f < N_FACTORS; f++) {
                const float4 lt = *(const float4*)&s_lat[f * CHANNEL + li * 4];
                float d = ue.x * lt.x + ue.y * lt.y + ue.z * lt.z + ue.w * lt.w;
                #pragma unroll
                for (int o = 8; o > 0; o >>= 1)
                    d += __shfl_xor_sync(0xFFFFFFFFu, d, o);
                s[f] = d;
            }
            float m = fmaxf(fmaxf(s[0], s[1]), fmaxf(s[2], s[3]));
            float sum = 0.0f;
            #pragma unroll
            for (int f = 0; f < N_FACTORS; f++) { s[f] = __expf(s[f] - m); sum += s[f]; }
            float inv = 1.0f / sum;

            float4 c = make_float4(0.f, 0.f, 0.f, 0.f);
            #pragma unroll
            for (int f = 0; f < N_FACTORS; f++) {
                float sc = s[f] * inv;
                const float4 dw = *(const float4*)&s_dis[f * CHANNEL + li * 4];
                c.x += sc * dw.x;
                c.y += sc * dw.y;
                c.z += sc * dw.z;
                c.w += sc * dw.w;
            }

            if (half == 0) {
                float4* o = (float4*)&out_user[(size_t)u * CHANNEL + li * 4];
                *o = make_float4(acc.x * (1.0f + c.x), acc.y * (1.0f + c.y),
                                 acc.z * (1.0f + c.z), acc.w * (1.0f + c.w));
            }
            if (lane == 0) g_ucnt[u] = 0;      // reset after consumption
        }
    }
}

// ---------------------------------------------------------------------------
extern "C" void kernel_launch(void* const* d_in, const int* in_sizes, int n_in,
                              void* d_out, int out_size)
{
    const float* entity_emb = (const float*)d_in[0];
    const float* user_emb   = (const float*)d_in[1];
    const float* latent_emb = (const float*)d_in[2];
    const int*   head       = (const int*)d_in[3];
    const int*   tail       = (const int*)d_in[4];
    const int*   edge_type  = (const int*)d_in[5];
    const int*   mat_row    = (const int*)d_in[6];
    const int*   mat_col    = (const int*)d_in[7];
    const float* mat_val    = (const float*)d_in[8];
    const float* rel_w      = (const float*)d_in[9];
    const float* weight     = (const float*)d_in[10];
    const float* disen_att  = (const float*)d_in[11];

    float* out      = (float*)d_out;
    float* out_ent  = out;                                 // (N_ENTITIES, 64)
    float* out_user = out + (size_t)N_ENTITIES * CHANNEL;  // (N_USERS, 64)

    k1_kernel<<<K1_BLOCKS, 256>>>(entity_emb, head, tail, edge_type,
                                  mat_row, mat_col, mat_val,
                                  rel_w, disen_att, weight);

    k2_kernel<<<K2_BLOCKS, 256>>>(entity_emb, user_emb, latent_emb,
                                  rel_w, out_ent, out_user);
}